// round 7
// baseline (speedup 1.0000x reference)
#include <cuda_runtime.h>
#include <cuda_bf16.h>
#include <cstdint>
#include <cstddef>

#define VOCAB 32000
#define HID   1024
#define EMB   512
#define RANK  64
#define BATCH 16
#define SEQLEN 256
#define NTOK  (BATCH*SEQLEN)
#define KCAT  3072

#define RNN_BLOCKS 128
#define OFF_V 0
#define OFF_A 9216
#define OFF_C 18432
#define OFF_H 18952
#define OFF_G 35336
#define OFF_R 36376
#define RNN_SMEM_FLOATS 40728
#define RNN_SMEM_BYTES  (RNN_SMEM_FLOATS*4)

__device__ __align__(16) float g_XU[NTOK*HID];
__device__ __align__(16) float g_XB[NTOK*RANK];
__device__ __align__(16) float g_h[2][BATCH*HID];
__device__ __align__(16) float g_gbuf[BATCH*RANK];
__device__ __align__(16) __nv_bfloat16 g_Acat[(size_t)NTOK*KCAT];
__device__ __align__(16) __nv_bfloat16 g_Bcat[(size_t)VOCAB*KCAT];
__device__ unsigned g_bar_arrive = 0;
__device__ unsigned g_bar_gen    = 0;

__device__ __forceinline__ void grid_bar() {
    __threadfence();
    __syncthreads();
    if (threadIdx.x == 0) {
        volatile unsigned* genp = (volatile unsigned*)&g_bar_gen;
        unsigned gen = *genp;
        unsigned arrived = atomicAdd(&g_bar_arrive, 1u);
        if (arrived == RNN_BLOCKS - 1) {
            atomicExch(&g_bar_arrive, 0u);
            __threadfence();
            atomicAdd(&g_bar_gen, 1u);
        } else {
            while (*genp == gen) { }
            __threadfence();
        }
    }
    __syncthreads();
}

// ======================= precompute: XU, XB ================================
template <int N_, bool HAS_BIAS>
__global__ __launch_bounds__(256) void gather_gemm(const int* __restrict__ inp,
                                                   const float* __restrict__ emb,
                                                   const float* __restrict__ W,
                                                   const float* __restrict__ bias) {
    __shared__ float As[16][65];
    __shared__ float Bs[16][68];
    __shared__ int   toks[64];
    float* outp = (N_ == RANK) ? g_XB : g_XU;

    const int tid = threadIdx.x;
    const int m0 = blockIdx.x * 64, n0 = blockIdx.y * 64;
    if (tid < 64) {
        int m = m0 + tid;
        toks[tid] = inp[(m & 15) * SEQLEN + (m >> 4)];
    }
    __syncthreads();

    const int ty = tid >> 4, tx = tid & 15;
    const int am = tid >> 2, akq = tid & 3;
    const int bk = tid >> 4, bn = tid & 15;
    float acc[4][4] = {};

    for (int k0 = 0; k0 < EMB; k0 += 16) {
        float4 av = *(const float4*)&emb[(size_t)toks[am] * EMB + k0 + akq * 4];
        float4 bv = *(const float4*)&W[(size_t)(k0 + bk) * N_ + n0 + bn * 4];
        __syncthreads();
        As[akq*4+0][am] = av.x; As[akq*4+1][am] = av.y;
        As[akq*4+2][am] = av.z; As[akq*4+3][am] = av.w;
        *(float4*)&Bs[bk][bn*4] = bv;
        __syncthreads();
#pragma unroll
        for (int kk = 0; kk < 16; kk++) {
            float a0 = As[kk][ty*4+0], a1 = As[kk][ty*4+1];
            float a2 = As[kk][ty*4+2], a3 = As[kk][ty*4+3];
            float4 b4 = *(const float4*)&Bs[kk][tx*4];
            acc[0][0] += a0*b4.x; acc[0][1] += a0*b4.y; acc[0][2] += a0*b4.z; acc[0][3] += a0*b4.w;
            acc[1][0] += a1*b4.x; acc[1][1] += a1*b4.y; acc[1][2] += a1*b4.z; acc[1][3] += a1*b4.w;
            acc[2][0] += a2*b4.x; acc[2][1] += a2*b4.y; acc[2][2] += a2*b4.z; acc[2][3] += a2*b4.w;
            acc[3][0] += a3*b4.x; acc[3][1] += a3*b4.y; acc[3][2] += a3*b4.z; acc[3][3] += a3*b4.w;
        }
    }

    float4 bb = make_float4(0.f,0.f,0.f,0.f);
    if (HAS_BIAS) bb = *(const float4*)&bias[n0 + tx*4];
#pragma unroll
    for (int i = 0; i < 4; i++) {
        int m = m0 + ty*4 + i;
        float4 o = make_float4(acc[i][0]+bb.x, acc[i][1]+bb.y, acc[i][2]+bb.z, acc[i][3]+bb.w);
        *(float4*)&outp[(size_t)m * N_ + n0 + tx*4] = o;
    }
}

// ======================= recurrence (writes Acat directly) =================
__global__ __launch_bounds__(256) void rnn_kernel(const float* __restrict__ A,
                                                  const float* __restrict__ C,
                                                  const float* __restrict__ V) {
    extern __shared__ float sm[];
    float* Vs  = sm + OFF_V;
    float* Asm = sm + OFF_A;
    float* Cs  = sm + OFF_C;
    float* hs  = sm + OFF_H;
    float* gs  = sm + OFF_G;
    float* red = sm + OFF_R;

    const int c = blockIdx.x, tid = threadIdx.x;
    const int col0  = c * 8;
    const int rbase = (c & 7) * 8;
    const int bmine = c >> 3;

    for (int idx = tid; idx < 8192; idx += 256) {
        int j = idx >> 3, q = idx & 7;
        Vs[j*9 + q]  = V[(size_t)j*HID + col0 + q];
        Asm[j*9 + q] = A[j*RANK + rbase + q];
    }
    for (int idx = tid; idx < 512; idx += 256) {
        int ci = idx >> 6, r = idx & 63;
        Cs[ci*65 + r] = C[(col0 + ci)*RANK + r];
    }
    if (tid < 128) g_h[0][c*128 + tid] = 0.0f;
    __syncthreads();
    grid_bar();

    const int kg = tid & 31, rem = tid >> 5;
    const int cg = rem & 1, bg = rem >> 1;
    const int w = rem, lane = kg;

    for (int t = 0; t < SEQLEN; t++) {
        const int p = t & 1;
        {
            const float* hrow = g_h[p] + bmine * HID;
            float s = 0.f;
#pragma unroll 8
            for (int j = lane; j < HID; j += 32)
                s += __ldcg(hrow + j) * Asm[j*9 + w];
#pragma unroll
            for (int off = 16; off; off >>= 1)
                s += __shfl_xor_sync(0xffffffffu, s, off);
            if (lane == 0) {
                int r = rbase + w;
                float gv = s * __ldcg(&g_XB[((size_t)t*BATCH + bmine)*RANK + r]);
                __stcg(&g_gbuf[bmine*RANK + r], gv);
            }
        }
        grid_bar();
        {
            const float4* hsrc = (const float4*)g_h[p];
            float4* hdst = (float4*)hs;
            for (int idx = tid; idx < 4096; idx += 256)
                hdst[idx] = __ldcg(hsrc + idx);
            for (int idx = tid; idx < 1024; idx += 256)
                gs[(idx >> 6)*65 + (idx & 63)] = __ldcg(&g_gbuf[idx]);
            __syncthreads();

            float acc[4][4] = {};
#pragma unroll 4
            for (int jj = 0; jj < 32; jj++) {
                int j = jj*32 + kg;
                float v0 = Vs[j*9 + cg*4 + 0], v1 = Vs[j*9 + cg*4 + 1];
                float v2 = Vs[j*9 + cg*4 + 2], v3 = Vs[j*9 + cg*4 + 3];
                float h0 = hs[(bg*4+0)*HID + j], h1 = hs[(bg*4+1)*HID + j];
                float h2 = hs[(bg*4+2)*HID + j], h3 = hs[(bg*4+3)*HID + j];
                acc[0][0] += h0*v0; acc[0][1] += h0*v1; acc[0][2] += h0*v2; acc[0][3] += h0*v3;
                acc[1][0] += h1*v0; acc[1][1] += h1*v1; acc[1][2] += h1*v2; acc[1][3] += h1*v3;
                acc[2][0] += h2*v0; acc[2][1] += h2*v1; acc[2][2] += h2*v2; acc[2][3] += h2*v3;
                acc[3][0] += h3*v0; acc[3][1] += h3*v1; acc[3][2] += h3*v2; acc[3][3] += h3*v3;
            }
#pragma unroll
            for (int bb = 0; bb < 4; bb++)
#pragma unroll
                for (int cc = 0; cc < 4; cc++)
                    red[tid*17 + bb*4 + cc] = acc[bb][cc];
            __syncthreads();

            if (tid < 128) {
                int remo = tid >> 4, idx = tid & 15;
                int bb = idx >> 2, cc = idx & 3;
                int ci = (remo & 1)*4 + cc;
                int b  = (remo >> 1)*4 + bb;
                int i  = col0 + ci;
                float s = 0.f;
#pragma unroll 8
                for (int k2 = 0; k2 < 32; k2++)
                    s += red[(remo*32 + k2)*17 + idx];
#pragma unroll 16
                for (int r = 0; r < RANK; r++)
                    s += gs[b*65 + r] * Cs[ci*65 + r];
                s += __ldg(&g_XU[((size_t)t*BATCH + b)*HID + i]);
                float hn = tanhf(s);
                __stcg(&g_h[p^1][b*HID + i], hn);
                // fused bf16x3 operand write (Acat row m = t*16+b)
                __nv_bfloat16 hi = __float2bfloat16(hn);
                __nv_bfloat16 lo = __float2bfloat16(hn - __bfloat162float(hi));
                size_t mb = ((size_t)t*BATCH + b) * KCAT;
                g_Acat[mb + i]        = hi;
                g_Acat[mb + 1024 + i] = lo;
                g_Acat[mb + 2048 + i] = hi;
            }
        }
        grid_bar();
    }
}

// ======================= W operand preparation =============================
__global__ __launch_bounds__(256) void conv_W(const float* __restrict__ W) {
    __shared__ float tile[32][33];
    const int bx = blockIdx.x, by = blockIdx.y;
    const int tx = threadIdx.x & 31, ty = threadIdx.x >> 5;
    int n = bx*32 + tx;
#pragma unroll
    for (int r = 0; r < 32; r += 8) {
        int k = by*32 + ty + r;
        tile[ty + r][tx] = W[(size_t)k*VOCAB + n];
    }
    __syncthreads();
#pragma unroll
    for (int r = 0; r < 32; r += 8) {
        int n2 = bx*32 + ty + r;
        int k2 = by*32 + tx;
        float f = tile[tx][ty + r];
        __nv_bfloat16 hi = __float2bfloat16(f);
        __nv_bfloat16 lo = __float2bfloat16(f - __bfloat162float(hi));
        size_t base = (size_t)n2 * KCAT;
        g_Bcat[base + k2]        = hi;
        g_Bcat[base + 1024 + k2] = hi;
        g_Bcat[base + 2048 + k2] = lo;
    }
}

// ======================= HMMA decoder GEMM =================================
// C[4096,32000] = Acat[4096,3072] @ Bcat[32000,3072]^T, fp32 accum.
// CTA 128x256, BK=32, 4-stage cp.async, 8 warps (2x4), warp tile 64x64.
#define DEC_STAGES 4
#define DEC_A_BYTES (128*80)               // 10240
#define DEC_B_BYTES (256*80)               // 20480
#define DEC_STG (DEC_A_BYTES + DEC_B_BYTES)
#define DEC_SMEM (1024 + DEC_STAGES*DEC_STG)
#define DEC_NCHUNK (KCAT/32)               // 96

__device__ __forceinline__ uint32_t s2u(const void* p) {
    uint32_t a;
    asm("{ .reg .u64 t; cvta.to.shared.u64 t, %1; cvt.u32.u64 %0, t; }" : "=r"(a) : "l"(p));
    return a;
}
__device__ __forceinline__ void cp16(uint32_t dst, const void* src) {
    asm volatile("cp.async.cg.shared.global [%0], [%1], 16;" :: "r"(dst), "l"(src));
}
__device__ __forceinline__ void cp_commit() {
    asm volatile("cp.async.commit_group;" ::: "memory");
}
template <int N> __device__ __forceinline__ void cp_wait() {
    asm volatile("cp.async.wait_group %0;" :: "n"(N) : "memory");
}
__device__ __forceinline__ void ldmx4(uint32_t* r, uint32_t a) {
    asm volatile("ldmatrix.sync.aligned.m8n8.x4.shared.b16 {%0,%1,%2,%3}, [%4];"
        : "=r"(r[0]), "=r"(r[1]), "=r"(r[2]), "=r"(r[3]) : "r"(a));
}
__device__ __forceinline__ void mma16816(float* c, const uint32_t* a, uint32_t b0, uint32_t b1) {
    asm volatile("mma.sync.aligned.m16n8k16.row.col.f32.bf16.bf16.f32 "
        "{%0,%1,%2,%3}, {%4,%5,%6,%7}, {%8,%9}, {%0,%1,%2,%3};"
        : "+f"(c[0]), "+f"(c[1]), "+f"(c[2]), "+f"(c[3])
        : "r"(a[0]), "r"(a[1]), "r"(a[2]), "r"(a[3]), "r"(b0), "r"(b1));
}

__device__ __forceinline__ void dec_load(uint32_t base, const char* Ag, const char* Bg,
                                         size_t koff, int r_, int seg) {
#pragma unroll
    for (int j = 0; j < 2; j++) {
        int r = r_ + j*64;
        cp16(base + r*80 + seg*16, Ag + (size_t)r*(KCAT*2) + koff + seg*16);
    }
#pragma unroll
    for (int j = 0; j < 4; j++) {
        int r = r_ + j*64;
        cp16(base + DEC_A_BYTES + r*80 + seg*16, Bg + (size_t)r*(KCAT*2) + koff + seg*16);
    }
}

__global__ void __launch_bounds__(256, 1) decoder_hmma(const float* __restrict__ bias,
                                                       float* __restrict__ out) {
    extern __shared__ __align__(16) char smem[];
    float* sbias = (float*)smem;
    const uint32_t D0 = s2u(smem) + 1024;
    const int tid = threadIdx.x;
    const int wid = tid >> 5, lid = tid & 31;
    const int m0 = blockIdx.x * 128, n0 = blockIdx.y * 256;
    const int wm = wid >> 2, wn = wid & 3;

    sbias[tid] = bias[n0 + tid];

    const char* Ag = (const char*)(g_Acat + (size_t)m0 * KCAT);
    const char* Bg = (const char*)(g_Bcat + (size_t)n0 * KCAT);
    const int r_ = tid >> 2, seg = tid & 3;

    float acc[4][8][4];
#pragma unroll
    for (int mi = 0; mi < 4; mi++)
#pragma unroll
        for (int ni = 0; ni < 8; ni++)
#pragma unroll
            for (int q = 0; q < 4; q++) acc[mi][ni][q] = 0.f;

    // prologue: stages 0..2
#pragma unroll
    for (int s = 0; s < DEC_STAGES - 1; s++) {
        dec_load(D0 + s*DEC_STG, Ag, Bg, (size_t)s*64, r_, seg);
        cp_commit();
    }

    const int quad = lid >> 3, r8 = lid & 7;
    const uint32_t a_row = wm*64 + (quad & 1)*8 + r8;
    const uint32_t a_kb  = (quad >> 1) * 16;
    const uint32_t b_row = wn*64 + (quad >> 1)*8 + r8;
    const uint32_t b_kb  = (quad & 1) * 16;

    for (int kc = 0; kc < DEC_NCHUNK; kc++) {
        const int s = kc & (DEC_STAGES - 1);
        cp_wait<DEC_STAGES - 2>();
        __syncthreads();
        if (kc + DEC_STAGES - 1 < DEC_NCHUNK) {
            dec_load(D0 + ((kc + DEC_STAGES - 1) & (DEC_STAGES - 1))*DEC_STG,
                     Ag, Bg, (size_t)(kc + DEC_STAGES - 1)*64, r_, seg);
        }
        cp_commit();

        const uint32_t sA = D0 + s*DEC_STG;
        const uint32_t sB = sA + DEC_A_BYTES;
#pragma unroll
        for (int kk = 0; kk < 2; kk++) {
            uint32_t Af[4][4], Bf[4][4];
#pragma unroll
            for (int mi = 0; mi < 4; mi++)
                ldmx4(Af[mi], sA + (a_row + mi*16)*80 + kk*32 + a_kb);
#pragma unroll
            for (int p = 0; p < 4; p++)
                ldmx4(Bf[p], sB + (b_row + p*16)*80 + kk*32 + b_kb);
#pragma unroll
            for (int mi = 0; mi < 4; mi++)
#pragma unroll
                for (int ni = 0; ni < 8; ni++)
                    mma16816(acc[mi][ni], Af[mi],
                             Bf[ni >> 1][(ni & 1)*2 + 0],
                             Bf[ni >> 1][(ni & 1)*2 + 1]);
        }
    }
    cp_wait<0>();

    // epilogue: bias + row remap (m = t*16+b -> out row b*256+t)
#pragma unroll
    for (int mi = 0; mi < 4; mi++) {
        int mA = m0 + wm*64 + mi*16 + (lid >> 2);
        int mB = mA + 8;
        float* oA = out + (size_t)((mA & 15)*SEQLEN + (mA >> 4)) * VOCAB + n0;
        float* oB = out + (size_t)((mB & 15)*SEQLEN + (mB >> 4)) * VOCAB + n0;
#pragma unroll
        for (int ni = 0; ni < 8; ni++) {
            int col = wn*64 + ni*8 + 2*(lid & 3);
            float2 vA = make_float2(acc[mi][ni][0] + sbias[col], acc[mi][ni][1] + sbias[col+1]);
            float2 vB = make_float2(acc[mi][ni][2] + sbias[col], acc[mi][ni][3] + sbias[col+1]);
            *(float2*)(oA + col) = vA;
            *(float2*)(oB + col) = vB;
        }
    }
}

// ======================= launch ============================================
extern "C" void kernel_launch(void* const* d_in, const int* in_sizes, int n_in,
                              void* d_out, int out_size) {
    const int*   inp = (const int*)d_in[0];
    const float* emb = (const float*)d_in[1];
    const float* A   = (const float*)d_in[2];
    const float* B   = (const float*)d_in[3];
    const float* C   = (const float*)d_in[4];
    const float* U   = (const float*)d_in[5];
    const float* V   = (const float*)d_in[6];
    const float* dv  = (const float*)d_in[7];
    const float* Wd  = (const float*)d_in[8];
    const float* bd  = (const float*)d_in[9];
    float* out = (float*)d_out;

    cudaFuncSetAttribute(rnn_kernel, cudaFuncAttributeMaxDynamicSharedMemorySize,
                         RNN_SMEM_BYTES);
    cudaFuncSetAttribute(decoder_hmma, cudaFuncAttributeMaxDynamicSharedMemorySize,
                         DEC_SMEM);

    conv_W<<<dim3(VOCAB/32, HID/32), 256>>>(Wd);

    dim3 gXU(NTOK/64, HID/64);
    gather_gemm<HID, true><<<gXU, 256>>>(inp, emb, U, dv);
    dim3 gXB(NTOK/64, RANK/64);
    gather_gemm<RANK, false><<<gXB, 256>>>(inp, emb, B, nullptr);

    rnn_kernel<<<RNN_BLOCKS, 256, RNN_SMEM_BYTES>>>(A, C, V);

    dim3 gDec(NTOK/128, VOCAB/256);
    decoder_hmma<<<gDec, 256, DEC_SMEM>>>(bd, out);
}

// round 8
// speedup vs baseline: 1.1374x; 1.1374x over previous
#include <cuda_runtime.h>
#include <cuda_bf16.h>
#include <cstdint>
#include <cstddef>

#define VOCAB 32000
#define HID   1024
#define EMB   512
#define RANK  64
#define BATCH 16
#define SEQLEN 256
#define NTOK  (BATCH*SEQLEN)
#define KCAT  3072

#define RNN_BLOCKS 128
// smem (floats): Vs 8*1032 colmajor, Asm 1024*9, Cs 8*65, hs 16*1024, gs 16*65, red 256*33
#define OFF_V 0
#define OFF_A 8256
#define OFF_C 17472
#define OFF_H 17992
#define OFF_G 34376
#define OFF_R 35416
#define RNN_SMEM_FLOATS 43864
#define RNN_SMEM_BYTES  (RNN_SMEM_FLOATS*4)

__device__ __align__(16) float g_XU[NTOK*HID];
__device__ __align__(16) float g_XB[NTOK*RANK];
__device__ __align__(16) float g_h[2][BATCH*HID];
__device__ __align__(16) float g_gbuf[BATCH*RANK];
__device__ __align__(16) __nv_bfloat16 g_Acat[(size_t)NTOK*KCAT];
__device__ __align__(16) __nv_bfloat16 g_Bcat[(size_t)VOCAB*KCAT];
__device__ unsigned g_bar_arrive = 0;
__device__ unsigned g_bar_gen    = 0;

__device__ __forceinline__ void grid_bar() {
    __threadfence();
    __syncthreads();
    if (threadIdx.x == 0) {
        volatile unsigned* genp = (volatile unsigned*)&g_bar_gen;
        unsigned gen = *genp;
        unsigned arrived = atomicAdd(&g_bar_arrive, 1u);
        if (arrived == RNN_BLOCKS - 1) {
            atomicExch(&g_bar_arrive, 0u);
            __threadfence();
            atomicAdd(&g_bar_gen, 1u);
        } else {
            while (*genp == gen) { }
            __threadfence();
        }
    }
    __syncthreads();
}

// ======================= precompute: XU, XB ================================
template <int N_, bool HAS_BIAS>
__global__ __launch_bounds__(256) void gather_gemm(const int* __restrict__ inp,
                                                   const float* __restrict__ emb,
                                                   const float* __restrict__ W,
                                                   const float* __restrict__ bias) {
    __shared__ float As[16][65];
    __shared__ float Bs[16][68];
    __shared__ int   toks[64];
    float* outp = (N_ == RANK) ? g_XB : g_XU;

    const int tid = threadIdx.x;
    const int m0 = blockIdx.x * 64, n0 = blockIdx.y * 64;
    if (tid < 64) {
        int m = m0 + tid;
        toks[tid] = inp[(m & 15) * SEQLEN + (m >> 4)];
    }
    __syncthreads();

    const int ty = tid >> 4, tx = tid & 15;
    const int am = tid >> 2, akq = tid & 3;
    const int bk = tid >> 4, bn = tid & 15;
    float acc[4][4] = {};

    for (int k0 = 0; k0 < EMB; k0 += 16) {
        float4 av = *(const float4*)&emb[(size_t)toks[am] * EMB + k0 + akq * 4];
        float4 bv = *(const float4*)&W[(size_t)(k0 + bk) * N_ + n0 + bn * 4];
        __syncthreads();
        As[akq*4+0][am] = av.x; As[akq*4+1][am] = av.y;
        As[akq*4+2][am] = av.z; As[akq*4+3][am] = av.w;
        *(float4*)&Bs[bk][bn*4] = bv;
        __syncthreads();
#pragma unroll
        for (int kk = 0; kk < 16; kk++) {
            float a0 = As[kk][ty*4+0], a1 = As[kk][ty*4+1];
            float a2 = As[kk][ty*4+2], a3 = As[kk][ty*4+3];
            float4 b4 = *(const float4*)&Bs[kk][tx*4];
            acc[0][0] += a0*b4.x; acc[0][1] += a0*b4.y; acc[0][2] += a0*b4.z; acc[0][3] += a0*b4.w;
            acc[1][0] += a1*b4.x; acc[1][1] += a1*b4.y; acc[1][2] += a1*b4.z; acc[1][3] += a1*b4.w;
            acc[2][0] += a2*b4.x; acc[2][1] += a2*b4.y; acc[2][2] += a2*b4.z; acc[2][3] += a2*b4.w;
            acc[3][0] += a3*b4.x; acc[3][1] += a3*b4.y; acc[3][2] += a3*b4.z; acc[3][3] += a3*b4.w;
        }
    }

    float4 bb = make_float4(0.f,0.f,0.f,0.f);
    if (HAS_BIAS) bb = *(const float4*)&bias[n0 + tx*4];
#pragma unroll
    for (int i = 0; i < 4; i++) {
        int m = m0 + ty*4 + i;
        float4 o = make_float4(acc[i][0]+bb.x, acc[i][1]+bb.y, acc[i][2]+bb.z, acc[i][3]+bb.w);
        *(float4*)&outp[(size_t)m * N_ + n0 + tx*4] = o;
    }
}

// ======================= recurrence ========================================
__global__ __launch_bounds__(256) void rnn_kernel(const float* __restrict__ A,
                                                  const float* __restrict__ C,
                                                  const float* __restrict__ V) {
    extern __shared__ float sm[];
    float* Vs  = sm + OFF_V;   // col-major: Vs[c*1032 + j]
    float* Asm = sm + OFF_A;   // [1024][9]
    float* Cs  = sm + OFF_C;   // [8][65]
    float* hs  = sm + OFF_H;   // [16][1024]
    float* gs  = sm + OFF_G;   // [16][65]
    float* red = sm + OFF_R;   // [256][33]

    const int c = blockIdx.x, tid = threadIdx.x;
    const int col0  = c * 8;
    const int rbase = (c & 7) * 8;
    const int bmine = c >> 3;

    for (int idx = tid; idx < 8192; idx += 256) {
        int cc = idx & 7, j = idx >> 3;
        Vs[cc*1032 + j] = V[(size_t)j*HID + col0 + cc];
        Asm[j*9 + cc]   = A[j*RANK + rbase + cc];
    }
    for (int idx = tid; idx < 512; idx += 256) {
        int ci = idx >> 6, r = idx & 63;
        Cs[ci*65 + r] = C[(col0 + ci)*RANK + r];
    }
    if (tid < 128) g_h[0][c*128 + tid] = 0.0f;
    __syncthreads();
    grid_bar();

    const int lane = tid & 31, w = tid >> 5;
    const int bg2 = tid >> 6, ks = (tid >> 5) & 1, kg2 = tid & 31;

    for (int t = 0; t < SEQLEN; t++) {
        const int p = t & 1;
        // phase 1: g[bmine, rbase+w] = (h@A) * XB
        {
            const float* hrow = g_h[p] + bmine * HID;
            float s = 0.f;
#pragma unroll 8
            for (int j = lane; j < HID; j += 32)
                s += __ldcg(hrow + j) * Asm[j*9 + w];
#pragma unroll
            for (int off = 16; off; off >>= 1)
                s += __shfl_xor_sync(0xffffffffu, s, off);
            if (lane == 0) {
                int r = rbase + w;
                float gv = s * __ldcg(&g_XB[((size_t)t*BATCH + bmine)*RANK + r]);
                __stcg(&g_gbuf[bmine*RANK + r], gv);
            }
        }
        grid_bar();
        // phase 2: h_new = tanh(XU + g@C^T + h@V) for this CTA's 8 cols
        {
            const float4* hsrc = (const float4*)g_h[p];
            float4* hdst = (float4*)hs;
            for (int idx = tid; idx < 4096; idx += 256)
                hdst[idx] = __ldcg(hsrc + idx);
            for (int idx = tid; idx < 1024; idx += 256)
                gs[(idx >> 6)*65 + (idx & 63)] = __ldcg(&g_gbuf[idx]);
            __syncthreads();

            // thread tile: 8 cols x 4 batches; j split over (ks, kg2, i, q)
            float acc[8][4];
#pragma unroll
            for (int cc = 0; cc < 8; cc++)
#pragma unroll
                for (int b4 = 0; b4 < 4; b4++) acc[cc][b4] = 0.f;

#pragma unroll
            for (int i = 0; i < 4; i++) {
                const int j0 = ks*512 + i*128 + kg2*4;
                float4 vv[8], hv[4];
#pragma unroll
                for (int cc = 0; cc < 8; cc++)
                    vv[cc] = *(const float4*)&Vs[cc*1032 + j0];
#pragma unroll
                for (int b4 = 0; b4 < 4; b4++)
                    hv[b4] = *(const float4*)&hs[(bg2*4 + b4)*1024 + j0];
#pragma unroll
                for (int cc = 0; cc < 8; cc++)
#pragma unroll
                    for (int b4 = 0; b4 < 4; b4++)
                        acc[cc][b4] += vv[cc].x*hv[b4].x + vv[cc].y*hv[b4].y
                                     + vv[cc].z*hv[b4].z + vv[cc].w*hv[b4].w;
            }
#pragma unroll
            for (int cc = 0; cc < 8; cc++)
#pragma unroll
                for (int b4 = 0; b4 < 4; b4++)
                    red[tid*33 + cc*4 + b4] = acc[cc][b4];
            __syncthreads();

            if (tid < 128) {
                const int b = tid >> 3, ci = tid & 7;
                const int bgo = b >> 2, slot = ci*4 + (b & 3);
                const int i = col0 + ci;
                float s = 0.f;
#pragma unroll 16
                for (int u = 0; u < 64; u++) {
                    int src = (bgo*2 + (u >> 5))*32 + (u & 31);
                    s += red[src*33 + slot];
                }
#pragma unroll 16
                for (int r = 0; r < RANK; r++)
                    s += gs[b*65 + r] * Cs[ci*65 + r];
                s += __ldg(&g_XU[((size_t)t*BATCH + b)*HID + i]);
                float hn = tanhf(s);
                __stcg(&g_h[p^1][b*HID + i], hn);
                __nv_bfloat16 hi = __float2bfloat16(hn);
                __nv_bfloat16 lo = __float2bfloat16(hn - __bfloat162float(hi));
                size_t mb = ((size_t)t*BATCH + b) * KCAT;
                g_Acat[mb + i]        = hi;
                g_Acat[mb + 1024 + i] = lo;
                g_Acat[mb + 2048 + i] = hi;
            }
        }
        grid_bar();
    }
}

// ======================= W operand preparation =============================
__global__ __launch_bounds__(256) void conv_W(const float* __restrict__ W) {
    __shared__ float tile[32][33];
    const int bx = blockIdx.x, by = blockIdx.y;
    const int tx = threadIdx.x & 31, ty = threadIdx.x >> 5;
    int n = bx*32 + tx;
#pragma unroll
    for (int r = 0; r < 32; r += 8) {
        int k = by*32 + ty + r;
        tile[ty + r][tx] = W[(size_t)k*VOCAB + n];
    }
    __syncthreads();
#pragma unroll
    for (int r = 0; r < 32; r += 8) {
        int n2 = bx*32 + ty + r;
        int k2 = by*32 + tx;
        float f = tile[tx][ty + r];
        __nv_bfloat16 hi = __float2bfloat16(f);
        __nv_bfloat16 lo = __float2bfloat16(f - __bfloat162float(hi));
        size_t base = (size_t)n2 * KCAT;
        g_Bcat[base + k2]        = hi;
        g_Bcat[base + 1024 + k2] = hi;
        g_Bcat[base + 2048 + k2] = lo;
    }
}

// ======================= HMMA decoder GEMM (round-5 proven) ================
// C[4096,32000] = Acat[4096,3072] @ Bcat[32000,3072]^T, fp32 accum.
// CTA 128x128, BK=32, 4-stage cp.async, 8 warps (4x2), warp tile 32x64.
#define DEC_STAGES 4
#define DEC_STG_BYTES 20480
#define DEC_SMEM (512 + DEC_STAGES*DEC_STG_BYTES)
#define DEC_NCHUNK (KCAT/32)

__device__ __forceinline__ uint32_t s2u(const void* p) {
    uint32_t a;
    asm("{ .reg .u64 t; cvta.to.shared.u64 t, %1; cvt.u32.u64 %0, t; }" : "=r"(a) : "l"(p));
    return a;
}
__device__ __forceinline__ void cp16(uint32_t dst, const void* src) {
    asm volatile("cp.async.cg.shared.global [%0], [%1], 16;" :: "r"(dst), "l"(src));
}
__device__ __forceinline__ void cp_commit() {
    asm volatile("cp.async.commit_group;" ::: "memory");
}
template <int N> __device__ __forceinline__ void cp_wait() {
    asm volatile("cp.async.wait_group %0;" :: "n"(N) : "memory");
}
__device__ __forceinline__ void ldmx4(uint32_t* r, uint32_t a) {
    asm volatile("ldmatrix.sync.aligned.m8n8.x4.shared.b16 {%0,%1,%2,%3}, [%4];"
        : "=r"(r[0]), "=r"(r[1]), "=r"(r[2]), "=r"(r[3]) : "r"(a));
}
__device__ __forceinline__ void mma16816(float* c, const uint32_t* a, uint32_t b0, uint32_t b1) {
    asm volatile("mma.sync.aligned.m16n8k16.row.col.f32.bf16.bf16.f32 "
        "{%0,%1,%2,%3}, {%4,%5,%6,%7}, {%8,%9}, {%0,%1,%2,%3};"
        : "+f"(c[0]), "+f"(c[1]), "+f"(c[2]), "+f"(c[3])
        : "r"(a[0]), "r"(a[1]), "r"(a[2]), "r"(a[3]), "r"(b0), "r"(b1));
}

__global__ void __launch_bounds__(256, 2) decoder_hmma(const float* __restrict__ bias,
                                                       float* __restrict__ out) {
    extern __shared__ __align__(16) char smem[];
    float* sbias = (float*)smem;
    const uint32_t D0 = s2u(smem) + 512;
    const int tid = threadIdx.x;
    const int wid = tid >> 5, lid = tid & 31;
    const int m0 = blockIdx.x * 128, n0 = blockIdx.y * 128;
    const int wm = wid >> 1, wn = wid & 1;

    if (tid < 128) sbias[tid] = bias[n0 + tid];

    const char* Ag = (const char*)(g_Acat + (size_t)m0 * KCAT);
    const char* Bg = (const char*)(g_Bcat + (size_t)n0 * KCAT);
    const int r_ = tid >> 2, seg = tid & 3;

    float acc[2][8][4];
#pragma unroll
    for (int i = 0; i < 2; i++)
#pragma unroll
        for (int j = 0; j < 8; j++)
#pragma unroll
            for (int q = 0; q < 4; q++) acc[i][j][q] = 0.f;

    // prologue: stages 0..2
#pragma unroll
    for (int s = 0; s < DEC_STAGES - 1; s++) {
        uint32_t base = D0 + s * DEC_STG_BYTES;
        size_t koff = (size_t)s * 64;
        cp16(base + r_*80 + seg*16,        Ag + (size_t)r_      * (KCAT*2) + koff + seg*16);
        cp16(base + (r_+64)*80 + seg*16,   Ag + (size_t)(r_+64) * (KCAT*2) + koff + seg*16);
        cp16(base + 10240 + r_*80 + seg*16,      Bg + (size_t)r_      * (KCAT*2) + koff + seg*16);
        cp16(base + 10240 + (r_+64)*80 + seg*16, Bg + (size_t)(r_+64) * (KCAT*2) + koff + seg*16);
        cp_commit();
    }

    const int quad = lid >> 3, r8 = lid & 7;
    const uint32_t a_row = wm*32 + (quad & 1)*8 + r8;
    const uint32_t a_kb  = (quad >> 1) * 16;
    const uint32_t b_row = wn*64 + (quad >> 1)*8 + r8;
    const uint32_t b_kb  = (quad & 1) * 16;

    for (int kc = 0; kc < DEC_NCHUNK; kc++) {
        const int s = kc & (DEC_STAGES - 1);
        cp_wait<DEC_STAGES - 2>();
        __syncthreads();
        if (kc + DEC_STAGES - 1 < DEC_NCHUNK) {
            const int ls = (kc + DEC_STAGES - 1) & (DEC_STAGES - 1);
            uint32_t base = D0 + ls * DEC_STG_BYTES;
            size_t koff = (size_t)(kc + DEC_STAGES - 1) * 64;
            cp16(base + r_*80 + seg*16,        Ag + (size_t)r_      * (KCAT*2) + koff + seg*16);
            cp16(base + (r_+64)*80 + seg*16,   Ag + (size_t)(r_+64) * (KCAT*2) + koff + seg*16);
            cp16(base + 10240 + r_*80 + seg*16,      Bg + (size_t)r_      * (KCAT*2) + koff + seg*16);
            cp16(base + 10240 + (r_+64)*80 + seg*16, Bg + (size_t)(r_+64) * (KCAT*2) + koff + seg*16);
        }
        cp_commit();

        const uint32_t sA = D0 + s * DEC_STG_BYTES;
        const uint32_t sB = sA + 10240;
#pragma unroll
        for (int kk = 0; kk < 2; kk++) {
            uint32_t A0[4], A1[4], Bf[4][4];
            uint32_t aaddr = sA + a_row*80 + kk*32 + a_kb;
            ldmx4(A0, aaddr);
            ldmx4(A1, aaddr + 16*80);
            uint32_t baddr = sB + b_row*80 + kk*32 + b_kb;
#pragma unroll
            for (int p = 0; p < 4; p++) ldmx4(Bf[p], baddr + p*16*80);
#pragma unroll
            for (int ni = 0; ni < 8; ni++) {
                uint32_t b0 = Bf[ni >> 1][(ni & 1)*2 + 0];
                uint32_t b1 = Bf[ni >> 1][(ni & 1)*2 + 1];
                mma16816(acc[0][ni], A0, b0, b1);
                mma16816(acc[1][ni], A1, b0, b1);
            }
        }
    }
    cp_wait<0>();

    // epilogue: bias + row remap (m = t*16+b -> out row b*256+t)
    const int mrow0 = m0 + wm*32 + (lid >> 2);
    const int ncol0 = wn*64 + 2*(lid & 3);
#pragma unroll
    for (int mi = 0; mi < 2; mi++) {
        int mA = mrow0 + mi*16, mB = mA + 8;
        float* oA = out + (size_t)((mA & 15)*SEQLEN + (mA >> 4)) * VOCAB + n0;
        float* oB = out + (size_t)((mB & 15)*SEQLEN + (mB >> 4)) * VOCAB + n0;
#pragma unroll
        for (int ni = 0; ni < 8; ni++) {
            int nn = ncol0 + ni*8;
            float2 vA = make_float2(acc[mi][ni][0] + sbias[nn], acc[mi][ni][1] + sbias[nn+1]);
            float2 vB = make_float2(acc[mi][ni][2] + sbias[nn], acc[mi][ni][3] + sbias[nn+1]);
            *(float2*)(oA + nn) = vA;
            *(float2*)(oB + nn) = vB;
        }
    }
}

// ======================= launch ============================================
extern "C" void kernel_launch(void* const* d_in, const int* in_sizes, int n_in,
                              void* d_out, int out_size) {
    const int*   inp = (const int*)d_in[0];
    const float* emb = (const float*)d_in[1];
    const float* A   = (const float*)d_in[2];
    const float* B   = (const float*)d_in[3];
    const float* C   = (const float*)d_in[4];
    const float* U   = (const float*)d_in[5];
    const float* V   = (const float*)d_in[6];
    const float* dv  = (const float*)d_in[7];
    const float* Wd  = (const float*)d_in[8];
    const float* bd  = (const float*)d_in[9];
    float* out = (float*)d_out;

    cudaFuncSetAttribute(rnn_kernel, cudaFuncAttributeMaxDynamicSharedMemorySize,
                         RNN_SMEM_BYTES);
    cudaFuncSetAttribute(decoder_hmma, cudaFuncAttributeMaxDynamicSharedMemorySize,
                         DEC_SMEM);

    conv_W<<<dim3(VOCAB/32, HID/32), 256>>>(Wd);

    dim3 gXU(NTOK/64, HID/64);
    gather_gemm<HID, true><<<gXU, 256>>>(inp, emb, U, dv);
    dim3 gXB(NTOK/64, RANK/64);
    gather_gemm<RANK, false><<<gXB, 256>>>(inp, emb, B, nullptr);

    rnn_kernel<<<RNN_BLOCKS, 256, RNN_SMEM_BYTES>>>(A, C, V);

    dim3 gDec(NTOK/128, VOCAB/128);
    decoder_hmma<<<gDec, 256, DEC_SMEM>>>(bd, out);
}

// round 9
// speedup vs baseline: 1.3206x; 1.1610x over previous
#include <cuda_runtime.h>
#include <cuda_fp16.h>
#include <cstdint>
#include <cstddef>

#define VOCAB 32000
#define HID   1024
#define EMB   512
#define RANK  64
#define BATCH 16
#define SEQLEN 256
#define NTOK  (BATCH*SEQLEN)
#define KA    2048          // A limbs: [Ah | Al] fp16
#define KB    1024          // B: single fp16 limb, read twice

#define RNN_BLOCKS 128
// smem (floats): Vs 8*1032 colmajor, Asm 1024*9, Cs 8*65, hs 16*1024, gs 16*65, red 256*33
#define OFF_V 0
#define OFF_A 8256
#define OFF_C 17472
#define OFF_H 17992
#define OFF_G 34376
#define OFF_R 35416
#define RNN_SMEM_FLOATS 43864
#define RNN_SMEM_BYTES  (RNN_SMEM_FLOATS*4)

__device__ __align__(16) float g_XU[NTOK*HID];
__device__ __align__(16) float g_XB[NTOK*RANK];
__device__ __align__(16) float g_h[2][BATCH*HID];
__device__ __align__(16) float g_gbuf[BATCH*RANK];
__device__ __align__(16) __half g_Acat[(size_t)NTOK*KA];
__device__ __align__(16) __half g_Bcat[(size_t)VOCAB*KB];
__device__ unsigned g_bar_arrive = 0;
__device__ unsigned g_bar_gen    = 0;

__device__ __forceinline__ void grid_bar() {
    __threadfence();
    __syncthreads();
    if (threadIdx.x == 0) {
        volatile unsigned* genp = (volatile unsigned*)&g_bar_gen;
        unsigned gen = *genp;
        unsigned arrived = atomicAdd(&g_bar_arrive, 1u);
        if (arrived == RNN_BLOCKS - 1) {
            atomicExch(&g_bar_arrive, 0u);
            __threadfence();
            atomicAdd(&g_bar_gen, 1u);
        } else {
            while (*genp == gen) { }
            __threadfence();
        }
    }
    __syncthreads();
}

// ======================= precompute: XU, XB ================================
template <int N_, bool HAS_BIAS>
__global__ __launch_bounds__(256) void gather_gemm(const int* __restrict__ inp,
                                                   const float* __restrict__ emb,
                                                   const float* __restrict__ W,
                                                   const float* __restrict__ bias) {
    __shared__ float As[16][65];
    __shared__ float Bs[16][68];
    __shared__ int   toks[64];
    float* outp = (N_ == RANK) ? g_XB : g_XU;

    const int tid = threadIdx.x;
    const int m0 = blockIdx.x * 64, n0 = blockIdx.y * 64;
    if (tid < 64) {
        int m = m0 + tid;
        toks[tid] = inp[(m & 15) * SEQLEN + (m >> 4)];
    }
    __syncthreads();

    const int ty = tid >> 4, tx = tid & 15;
    const int am = tid >> 2, akq = tid & 3;
    const int bk = tid >> 4, bn = tid & 15;
    float acc[4][4] = {};

    for (int k0 = 0; k0 < EMB; k0 += 16) {
        float4 av = *(const float4*)&emb[(size_t)toks[am] * EMB + k0 + akq * 4];
        float4 bv = *(const float4*)&W[(size_t)(k0 + bk) * N_ + n0 + bn * 4];
        __syncthreads();
        As[akq*4+0][am] = av.x; As[akq*4+1][am] = av.y;
        As[akq*4+2][am] = av.z; As[akq*4+3][am] = av.w;
        *(float4*)&Bs[bk][bn*4] = bv;
        __syncthreads();
#pragma unroll
        for (int kk = 0; kk < 16; kk++) {
            float a0 = As[kk][ty*4+0], a1 = As[kk][ty*4+1];
            float a2 = As[kk][ty*4+2], a3 = As[kk][ty*4+3];
            float4 b4 = *(const float4*)&Bs[kk][tx*4];
            acc[0][0] += a0*b4.x; acc[0][1] += a0*b4.y; acc[0][2] += a0*b4.z; acc[0][3] += a0*b4.w;
            acc[1][0] += a1*b4.x; acc[1][1] += a1*b4.y; acc[1][2] += a1*b4.z; acc[1][3] += a1*b4.w;
            acc[2][0] += a2*b4.x; acc[2][1] += a2*b4.y; acc[2][2] += a2*b4.z; acc[2][3] += a2*b4.w;
            acc[3][0] += a3*b4.x; acc[3][1] += a3*b4.y; acc[3][2] += a3*b4.z; acc[3][3] += a3*b4.w;
        }
    }

    float4 bb = make_float4(0.f,0.f,0.f,0.f);
    if (HAS_BIAS) bb = *(const float4*)&bias[n0 + tx*4];
#pragma unroll
    for (int i = 0; i < 4; i++) {
        int m = m0 + ty*4 + i;
        float4 o = make_float4(acc[i][0]+bb.x, acc[i][1]+bb.y, acc[i][2]+bb.z, acc[i][3]+bb.w);
        *(float4*)&outp[(size_t)m * N_ + n0 + tx*4] = o;
    }
}

// ======================= recurrence ========================================
__global__ __launch_bounds__(256) void rnn_kernel(const float* __restrict__ A,
                                                  const float* __restrict__ C,
                                                  const float* __restrict__ V) {
    extern __shared__ float sm[];
    float* Vs  = sm + OFF_V;   // col-major: Vs[c*1032 + j]
    float* Asm = sm + OFF_A;   // [1024][9]
    float* Cs  = sm + OFF_C;   // [8][65]
    float* hs  = sm + OFF_H;   // [16][1024]
    float* gs  = sm + OFF_G;   // [16][65]
    float* red = sm + OFF_R;   // [256][33]

    const int c = blockIdx.x, tid = threadIdx.x;
    const int col0  = c * 8;
    const int rbase = (c & 7) * 8;
    const int bmine = c >> 3;

    for (int idx = tid; idx < 8192; idx += 256) {
        int cc = idx & 7, j = idx >> 3;
        Vs[cc*1032 + j] = V[(size_t)j*HID + col0 + cc];
        Asm[j*9 + cc]   = A[j*RANK + rbase + cc];
    }
    for (int idx = tid; idx < 512; idx += 256) {
        int ci = idx >> 6, r = idx & 63;
        Cs[ci*65 + r] = C[(col0 + ci)*RANK + r];
    }
    if (tid < 128) g_h[0][c*128 + tid] = 0.0f;
    __syncthreads();
    grid_bar();

    const int lane = tid & 31, w = tid >> 5;
    const int bg2 = tid >> 6, ks = (tid >> 5) & 1, kg2 = tid & 31;

    for (int t = 0; t < SEQLEN; t++) {
        const int p = t & 1;
        // phase 1: g[bmine, rbase+w] = (h@A) * XB
        {
            const float* hrow = g_h[p] + bmine * HID;
            float s = 0.f;
#pragma unroll 8
            for (int j = lane; j < HID; j += 32)
                s += __ldcg(hrow + j) * Asm[j*9 + w];
#pragma unroll
            for (int off = 16; off; off >>= 1)
                s += __shfl_xor_sync(0xffffffffu, s, off);
            if (lane == 0) {
                int r = rbase + w;
                float gv = s * __ldcg(&g_XB[((size_t)t*BATCH + bmine)*RANK + r]);
                __stcg(&g_gbuf[bmine*RANK + r], gv);
            }
        }
        grid_bar();
        // phase 2: h_new = tanh(XU + g@C^T + h@V) for this CTA's 8 cols
        {
            const float4* hsrc = (const float4*)g_h[p];
            float4* hdst = (float4*)hs;
            for (int idx = tid; idx < 4096; idx += 256)
                hdst[idx] = __ldcg(hsrc + idx);
            for (int idx = tid; idx < 1024; idx += 256)
                gs[(idx >> 6)*65 + (idx & 63)] = __ldcg(&g_gbuf[idx]);
            __syncthreads();

            float acc[8][4];
#pragma unroll
            for (int cc = 0; cc < 8; cc++)
#pragma unroll
                for (int b4 = 0; b4 < 4; b4++) acc[cc][b4] = 0.f;

#pragma unroll
            for (int i = 0; i < 4; i++) {
                const int j0 = ks*512 + i*128 + kg2*4;
                float4 vv[8], hv[4];
#pragma unroll
                for (int cc = 0; cc < 8; cc++)
                    vv[cc] = *(const float4*)&Vs[cc*1032 + j0];
#pragma unroll
                for (int b4 = 0; b4 < 4; b4++)
                    hv[b4] = *(const float4*)&hs[(bg2*4 + b4)*1024 + j0];
#pragma unroll
                for (int cc = 0; cc < 8; cc++)
#pragma unroll
                    for (int b4 = 0; b4 < 4; b4++)
                        acc[cc][b4] += vv[cc].x*hv[b4].x + vv[cc].y*hv[b4].y
                                     + vv[cc].z*hv[b4].z + vv[cc].w*hv[b4].w;
            }
#pragma unroll
            for (int cc = 0; cc < 8; cc++)
#pragma unroll
                for (int b4 = 0; b4 < 4; b4++)
                    red[tid*33 + cc*4 + b4] = acc[cc][b4];
            __syncthreads();

            if (tid < 128) {
                const int b = tid >> 3, ci = tid & 7;
                const int bgo = b >> 2, slot = ci*4 + (b & 3);
                const int i = col0 + ci;
                float s = 0.f;
#pragma unroll 16
                for (int u = 0; u < 64; u++) {
                    int src = (bgo*2 + (u >> 5))*32 + (u & 31);
                    s += red[src*33 + slot];
                }
#pragma unroll 16
                for (int r = 0; r < RANK; r++)
                    s += gs[b*65 + r] * Cs[ci*65 + r];
                s += __ldg(&g_XU[((size_t)t*BATCH + b)*HID + i]);
                float hn = tanhf(s);
                __stcg(&g_h[p^1][b*HID + i], hn);
                // fused fp16 2-limb operand write (Acat row m = t*16+b)
                __half hi = __float2half(hn);
                __half lo = __float2half(hn - __half2float(hi));
                size_t mb = ((size_t)t*BATCH + b) * KA;
                g_Acat[mb + i]        = hi;
                g_Acat[mb + 1024 + i] = lo;
            }
        }
        grid_bar();
    }
}

// ======================= W operand preparation =============================
// Bcat[n][k] = fp16(W_dec[k][n])  (transpose to k-major, single limb)
__global__ __launch_bounds__(256) void conv_W(const float* __restrict__ W) {
    __shared__ float tile[32][33];
    const int bx = blockIdx.x, by = blockIdx.y;
    const int tx = threadIdx.x & 31, ty = threadIdx.x >> 5;
    int n = bx*32 + tx;
#pragma unroll
    for (int r = 0; r < 32; r += 8) {
        int k = by*32 + ty + r;
        tile[ty + r][tx] = W[(size_t)k*VOCAB + n];
    }
    __syncthreads();
#pragma unroll
    for (int r = 0; r < 32; r += 8) {
        int n2 = bx*32 + ty + r;
        int k2 = by*32 + tx;
        g_Bcat[(size_t)n2*KB + k2] = __float2half(tile[tx][ty + r]);
    }
}

// ======================= HMMA decoder GEMM =================================
// C[4096,32000] = Acat[4096,2048] @ (Bh read twice)[32000,1024]^T, fp32 accum.
// CTA 128x128, BK=32, 4-stage cp.async, 8 warps (4x2), warp tile 32x64.
#define DEC_STAGES 4
#define DEC_STG_BYTES 20480
#define DEC_SMEM (512 + DEC_STAGES*DEC_STG_BYTES)
#define DEC_NCHUNK (KA/32)        // 64

__device__ __forceinline__ uint32_t s2u(const void* p) {
    uint32_t a;
    asm("{ .reg .u64 t; cvta.to.shared.u64 t, %1; cvt.u32.u64 %0, t; }" : "=r"(a) : "l"(p));
    return a;
}
__device__ __forceinline__ void cp16(uint32_t dst, const void* src) {
    asm volatile("cp.async.cg.shared.global [%0], [%1], 16;" :: "r"(dst), "l"(src));
}
__device__ __forceinline__ void cp_commit() {
    asm volatile("cp.async.commit_group;" ::: "memory");
}
template <int N> __device__ __forceinline__ void cp_wait() {
    asm volatile("cp.async.wait_group %0;" :: "n"(N) : "memory");
}
__device__ __forceinline__ void ldmx4(uint32_t* r, uint32_t a) {
    asm volatile("ldmatrix.sync.aligned.m8n8.x4.shared.b16 {%0,%1,%2,%3}, [%4];"
        : "=r"(r[0]), "=r"(r[1]), "=r"(r[2]), "=r"(r[3]) : "r"(a));
}
__device__ __forceinline__ void mma16816(float* c, const uint32_t* a, uint32_t b0, uint32_t b1) {
    asm volatile("mma.sync.aligned.m16n8k16.row.col.f32.f16.f16.f32 "
        "{%0,%1,%2,%3}, {%4,%5,%6,%7}, {%8,%9}, {%0,%1,%2,%3};"
        : "+f"(c[0]), "+f"(c[1]), "+f"(c[2]), "+f"(c[3])
        : "r"(a[0]), "r"(a[1]), "r"(a[2]), "r"(a[3]), "r"(b0), "r"(b1));
}

__device__ __forceinline__ void dec_load(uint32_t base, const char* Ag, const char* Bg,
                                         int kc, int r_, int seg) {
    const size_t koffA = (size_t)kc * 64;
    const size_t koffB = (size_t)(kc & 31) * 64;   // B re-read for the Al pass
    cp16(base + r_*80 + seg*16,        Ag + (size_t)r_      * (KA*2) + koffA + seg*16);
    cp16(base + (r_+64)*80 + seg*16,   Ag + (size_t)(r_+64) * (KA*2) + koffA + seg*16);
    cp16(base + 10240 + r_*80 + seg*16,      Bg + (size_t)r_      * (KB*2) + koffB + seg*16);
    cp16(base + 10240 + (r_+64)*80 + seg*16, Bg + (size_t)(r_+64) * (KB*2) + koffB + seg*16);
}

__global__ void __launch_bounds__(256, 2) decoder_hmma(const float* __restrict__ bias,
                                                       float* __restrict__ out) {
    extern __shared__ __align__(16) char smem[];
    float* sbias = (float*)smem;
    const uint32_t D0 = s2u(smem) + 512;
    const int tid = threadIdx.x;
    const int wid = tid >> 5, lid = tid & 31;
    const int m0 = blockIdx.x * 128, n0 = blockIdx.y * 128;
    const int wm = wid >> 1, wn = wid & 1;

    if (tid < 128) sbias[tid] = bias[n0 + tid];

    const char* Ag = (const char*)(g_Acat + (size_t)m0 * KA);
    const char* Bg = (const char*)(g_Bcat + (size_t)n0 * KB);
    const int r_ = tid >> 2, seg = tid & 3;

    float acc[2][8][4];
#pragma unroll
    for (int i = 0; i < 2; i++)
#pragma unroll
        for (int j = 0; j < 8; j++)
#pragma unroll
            for (int q = 0; q < 4; q++) acc[i][j][q] = 0.f;

    // prologue: stages 0..2
#pragma unroll
    for (int s = 0; s < DEC_STAGES - 1; s++) {
        dec_load(D0 + s*DEC_STG_BYTES, Ag, Bg, s, r_, seg);
        cp_commit();
    }

    const int quad = lid >> 3, r8 = lid & 7;
    const uint32_t a_row = wm*32 + (quad & 1)*8 + r8;
    const uint32_t a_kb  = (quad >> 1) * 16;
    const uint32_t b_row = wn*64 + (quad >> 1)*8 + r8;
    const uint32_t b_kb  = (quad & 1) * 16;

    for (int kc = 0; kc < DEC_NCHUNK; kc++) {
        const int s = kc & (DEC_STAGES - 1);
        cp_wait<DEC_STAGES - 2>();
        __syncthreads();
        if (kc + DEC_STAGES - 1 < DEC_NCHUNK) {
            dec_load(D0 + ((kc + DEC_STAGES - 1) & (DEC_STAGES - 1))*DEC_STG_BYTES,
                     Ag, Bg, kc + DEC_STAGES - 1, r_, seg);
        }
        cp_commit();

        const uint32_t sA = D0 + s * DEC_STG_BYTES;
        const uint32_t sB = sA + 10240;
#pragma unroll
        for (int kk = 0; kk < 2; kk++) {
            uint32_t A0[4], A1[4], Bf[4][4];
            uint32_t aaddr = sA + a_row*80 + kk*32 + a_kb;
            ldmx4(A0, aaddr);
            ldmx4(A1, aaddr + 16*80);
            uint32_t baddr = sB + b_row*80 + kk*32 + b_kb;
#pragma unroll
            for (int p = 0; p < 4; p++) ldmx4(Bf[p], baddr + p*16*80);
#pragma unroll
            for (int ni = 0; ni < 8; ni++) {
                uint32_t b0 = Bf[ni >> 1][(ni & 1)*2 + 0];
                uint32_t b1 = Bf[ni >> 1][(ni & 1)*2 + 1];
                mma16816(acc[0][ni], A0, b0, b1);
                mma16816(acc[1][ni], A1, b0, b1);
            }
        }
    }
    cp_wait<0>();

    // epilogue: bias + row remap (m = t*16+b -> out row b*256+t)
    const int mrow0 = m0 + wm*32 + (lid >> 2);
    const int ncol0 = wn*64 + 2*(lid & 3);
#pragma unroll
    for (int mi = 0; mi < 2; mi++) {
        int mA = mrow0 + mi*16, mB = mA + 8;
        float* oA = out + (size_t)((mA & 15)*SEQLEN + (mA >> 4)) * VOCAB + n0;
        float* oB = out + (size_t)((mB & 15)*SEQLEN + (mB >> 4)) * VOCAB + n0;
#pragma unroll
        for (int ni = 0; ni < 8; ni++) {
            int nn = ncol0 + ni*8;
            float2 vA = make_float2(acc[mi][ni][0] + sbias[nn], acc[mi][ni][1] + sbias[nn+1]);
            float2 vB = make_float2(acc[mi][ni][2] + sbias[nn], acc[mi][ni][3] + sbias[nn+1]);
            *(float2*)(oA + nn) = vA;
            *(float2*)(oB + nn) = vB;
        }
    }
}

// ======================= launch ============================================
extern "C" void kernel_launch(void* const* d_in, const int* in_sizes, int n_in,
                              void* d_out, int out_size) {
    const int*   inp = (const int*)d_in[0];
    const float* emb = (const float*)d_in[1];
    const float* A   = (const float*)d_in[2];
    const float* B   = (const float*)d_in[3];
    const float* C   = (const float*)d_in[4];
    const float* U   = (const float*)d_in[5];
    const float* V   = (const float*)d_in[6];
    const float* dv  = (const float*)d_in[7];
    const float* Wd  = (const float*)d_in[8];
    const float* bd  = (const float*)d_in[9];
    float* out = (float*)d_out;

    cudaFuncSetAttribute(rnn_kernel, cudaFuncAttributeMaxDynamicSharedMemorySize,
                         RNN_SMEM_BYTES);
    cudaFuncSetAttribute(decoder_hmma, cudaFuncAttributeMaxDynamicSharedMemorySize,
                         DEC_SMEM);

    conv_W<<<dim3(VOCAB/32, HID/32), 256>>>(Wd);

    dim3 gXU(NTOK/64, HID/64);
    gather_gemm<HID, true><<<gXU, 256>>>(inp, emb, U, dv);
    dim3 gXB(NTOK/64, RANK/64);
    gather_gemm<RANK, false><<<gXB, 256>>>(inp, emb, B, nullptr);

    rnn_kernel<<<RNN_BLOCKS, 256, RNN_SMEM_BYTES>>>(A, C, V);

    dim3 gDec(NTOK/128, VOCAB/128);
    decoder_hmma<<<gDec, 256, DEC_SMEM>>>(bd, out);
}

// round 10
// speedup vs baseline: 1.6160x; 1.2237x over previous
#include <cuda_runtime.h>
#include <cuda_fp16.h>
#include <cstdint>
#include <cstddef>

#define VOCAB 32000
#define HID   1024
#define EMB   512
#define RANK  64
#define BATCH 16
#define SEQLEN 256
#define NTOK  (BATCH*SEQLEN)
#define KA    1024          // A: single fp16 limb
#define KB    1024          // B: single fp16 limb

#define RNN_BLOCKS 128
// smem (floats): Vs 8*1032 colmajor, Asm 1024*9, Cs 8*65, hs 16*1024, gs 16*65, red 256*33
#define OFF_V 0
#define OFF_A 8256
#define OFF_C 17472
#define OFF_H 17992
#define OFF_G 34376
#define OFF_R 35416
#define RNN_SMEM_FLOATS 43864
#define RNN_SMEM_BYTES  (RNN_SMEM_FLOATS*4)

__device__ __align__(16) float g_XU[NTOK*HID];
__device__ __align__(16) float g_XB[NTOK*RANK];
__device__ __align__(16) float g_h[2][BATCH*HID];
__device__ __align__(16) float g_gbuf[BATCH*RANK];
__device__ __align__(16) __half g_Acat[(size_t)NTOK*KA];
__device__ __align__(16) __half g_Bcat[(size_t)VOCAB*KB];
__device__ unsigned g_bar_arrive = 0;
__device__ unsigned g_bar_gen    = 0;

__device__ __forceinline__ void grid_bar() {
    __threadfence();
    __syncthreads();
    if (threadIdx.x == 0) {
        volatile unsigned* genp = (volatile unsigned*)&g_bar_gen;
        unsigned gen = *genp;
        unsigned arrived = atomicAdd(&g_bar_arrive, 1u);
        if (arrived == RNN_BLOCKS - 1) {
            atomicExch(&g_bar_arrive, 0u);
            __threadfence();
            atomicAdd(&g_bar_gen, 1u);
        } else {
            while (*genp == gen) { }
            __threadfence();
        }
    }
    __syncthreads();
}

// ======================= precompute: XU, XB ================================
template <int N_, bool HAS_BIAS>
__global__ __launch_bounds__(256) void gather_gemm(const int* __restrict__ inp,
                                                   const float* __restrict__ emb,
                                                   const float* __restrict__ W,
                                                   const float* __restrict__ bias) {
    __shared__ float As[16][65];
    __shared__ float Bs[16][68];
    __shared__ int   toks[64];
    float* outp = (N_ == RANK) ? g_XB : g_XU;

    const int tid = threadIdx.x;
    const int m0 = blockIdx.x * 64, n0 = blockIdx.y * 64;
    if (tid < 64) {
        int m = m0 + tid;
        toks[tid] = inp[(m & 15) * SEQLEN + (m >> 4)];
    }
    __syncthreads();

    const int ty = tid >> 4, tx = tid & 15;
    const int am = tid >> 2, akq = tid & 3;
    const int bk = tid >> 4, bn = tid & 15;
    float acc[4][4] = {};

    for (int k0 = 0; k0 < EMB; k0 += 16) {
        float4 av = *(const float4*)&emb[(size_t)toks[am] * EMB + k0 + akq * 4];
        float4 bv = *(const float4*)&W[(size_t)(k0 + bk) * N_ + n0 + bn * 4];
        __syncthreads();
        As[akq*4+0][am] = av.x; As[akq*4+1][am] = av.y;
        As[akq*4+2][am] = av.z; As[akq*4+3][am] = av.w;
        *(float4*)&Bs[bk][bn*4] = bv;
        __syncthreads();
#pragma unroll
        for (int kk = 0; kk < 16; kk++) {
            float a0 = As[kk][ty*4+0], a1 = As[kk][ty*4+1];
            float a2 = As[kk][ty*4+2], a3 = As[kk][ty*4+3];
            float4 b4 = *(const float4*)&Bs[kk][tx*4];
            acc[0][0] += a0*b4.x; acc[0][1] += a0*b4.y; acc[0][2] += a0*b4.z; acc[0][3] += a0*b4.w;
            acc[1][0] += a1*b4.x; acc[1][1] += a1*b4.y; acc[1][2] += a1*b4.z; acc[1][3] += a1*b4.w;
            acc[2][0] += a2*b4.x; acc[2][1] += a2*b4.y; acc[2][2] += a2*b4.z; acc[2][3] += a2*b4.w;
            acc[3][0] += a3*b4.x; acc[3][1] += a3*b4.y; acc[3][2] += a3*b4.z; acc[3][3] += a3*b4.w;
        }
    }

    float4 bb = make_float4(0.f,0.f,0.f,0.f);
    if (HAS_BIAS) bb = *(const float4*)&bias[n0 + tx*4];
#pragma unroll
    for (int i = 0; i < 4; i++) {
        int m = m0 + ty*4 + i;
        float4 o = make_float4(acc[i][0]+bb.x, acc[i][1]+bb.y, acc[i][2]+bb.z, acc[i][3]+bb.w);
        *(float4*)&outp[(size_t)m * N_ + n0 + tx*4] = o;
    }
}

// ======================= recurrence ========================================
__global__ __launch_bounds__(256) void rnn_kernel(const float* __restrict__ A,
                                                  const float* __restrict__ C,
                                                  const float* __restrict__ V) {
    extern __shared__ float sm[];
    float* Vs  = sm + OFF_V;   // col-major: Vs[c*1032 + j]
    float* Asm = sm + OFF_A;   // [1024][9]
    float* Cs  = sm + OFF_C;   // [8][65]
    float* hs  = sm + OFF_H;   // [16][1024]
    float* gs  = sm + OFF_G;   // [16][65]
    float* red = sm + OFF_R;   // [256][33]

    const int c = blockIdx.x, tid = threadIdx.x;
    const int col0  = c * 8;
    const int rbase = (c & 7) * 8;
    const int bmine = c >> 3;

    for (int idx = tid; idx < 8192; idx += 256) {
        int cc = idx & 7, j = idx >> 3;
        Vs[cc*1032 + j] = V[(size_t)j*HID + col0 + cc];
        Asm[j*9 + cc]   = A[j*RANK + rbase + cc];
    }
    for (int idx = tid; idx < 512; idx += 256) {
        int ci = idx >> 6, r = idx & 63;
        Cs[ci*65 + r] = C[(col0 + ci)*RANK + r];
    }
    if (tid < 128) g_h[0][c*128 + tid] = 0.0f;
    __syncthreads();
    grid_bar();

    const int lane = tid & 31, w = tid >> 5;
    const int bg2 = tid >> 6, ks = (tid >> 5) & 1, kg2 = tid & 31;

    for (int t = 0; t < SEQLEN; t++) {
        const int p = t & 1;
        // phase 1: g[bmine, rbase+w] = (h@A) * XB
        {
            const float* hrow = g_h[p] + bmine * HID;
            float s = 0.f;
#pragma unroll 8
            for (int j = lane; j < HID; j += 32)
                s += __ldcg(hrow + j) * Asm[j*9 + w];
#pragma unroll
            for (int off = 16; off; off >>= 1)
                s += __shfl_xor_sync(0xffffffffu, s, off);
            if (lane == 0) {
                int r = rbase + w;
                float gv = s * __ldcg(&g_XB[((size_t)t*BATCH + bmine)*RANK + r]);
                __stcg(&g_gbuf[bmine*RANK + r], gv);
            }
        }
        grid_bar();
        // phase 2: h_new = tanh(XU + g@C^T + h@V) for this CTA's 8 cols
        {
            const float4* hsrc = (const float4*)g_h[p];
            float4* hdst = (float4*)hs;
            for (int idx = tid; idx < 4096; idx += 256)
                hdst[idx] = __ldcg(hsrc + idx);
            for (int idx = tid; idx < 1024; idx += 256)
                gs[(idx >> 6)*65 + (idx & 63)] = __ldcg(&g_gbuf[idx]);
            __syncthreads();

            float acc[8][4];
#pragma unroll
            for (int cc = 0; cc < 8; cc++)
#pragma unroll
                for (int b4 = 0; b4 < 4; b4++) acc[cc][b4] = 0.f;

#pragma unroll
            for (int i = 0; i < 4; i++) {
                const int j0 = ks*512 + i*128 + kg2*4;
                float4 vv[8], hv[4];
#pragma unroll
                for (int cc = 0; cc < 8; cc++)
                    vv[cc] = *(const float4*)&Vs[cc*1032 + j0];
#pragma unroll
                for (int b4 = 0; b4 < 4; b4++)
                    hv[b4] = *(const float4*)&hs[(bg2*4 + b4)*1024 + j0];
#pragma unroll
                for (int cc = 0; cc < 8; cc++)
#pragma unroll
                    for (int b4 = 0; b4 < 4; b4++)
                        acc[cc][b4] += vv[cc].x*hv[b4].x + vv[cc].y*hv[b4].y
                                     + vv[cc].z*hv[b4].z + vv[cc].w*hv[b4].w;
            }
#pragma unroll
            for (int cc = 0; cc < 8; cc++)
#pragma unroll
                for (int b4 = 0; b4 < 4; b4++)
                    red[tid*33 + cc*4 + b4] = acc[cc][b4];
            __syncthreads();

            if (tid < 128) {
                const int b = tid >> 3, ci = tid & 7;
                const int bgo = b >> 2, slot = ci*4 + (b & 3);
                const int i = col0 + ci;
                float s = 0.f;
#pragma unroll 16
                for (int u = 0; u < 64; u++) {
                    int src = (bgo*2 + (u >> 5))*32 + (u & 31);
                    s += red[src*33 + slot];
                }
#pragma unroll 16
                for (int r = 0; r < RANK; r++)
                    s += gs[b*65 + r] * Cs[ci*65 + r];
                s += __ldg(&g_XU[((size_t)t*BATCH + b)*HID + i]);
                float hn = tanhf(s);
                __stcg(&g_h[p^1][b*HID + i], hn);
                // fused fp16 operand write (Acat row m = t*16+b)
                g_Acat[((size_t)t*BATCH + b)*KA + i] = __float2half(hn);
            }
        }
        grid_bar();
    }
}

// ======================= W operand preparation =============================
// Bcat[n][k] = fp16(W_dec[k][n])  (transpose to k-major)
__global__ __launch_bounds__(256) void conv_W(const float* __restrict__ W) {
    __shared__ float tile[32][33];
    const int bx = blockIdx.x, by = blockIdx.y;
    const int tx = threadIdx.x & 31, ty = threadIdx.x >> 5;
    int n = bx*32 + tx;
#pragma unroll
    for (int r = 0; r < 32; r += 8) {
        int k = by*32 + ty + r;
        tile[ty + r][tx] = W[(size_t)k*VOCAB + n];
    }
    __syncthreads();
#pragma unroll
    for (int r = 0; r < 32; r += 8) {
        int n2 = bx*32 + ty + r;
        int k2 = by*32 + tx;
        g_Bcat[(size_t)n2*KB + k2] = __float2half(tile[tx][ty + r]);
    }
}

// ======================= HMMA decoder GEMM =================================
// C[4096,32000] = Acat[4096,1024] @ Bcat[32000,1024]^T, fp32 accum.
// CTA 128x128, BK=32, 4-stage cp.async, 8 warps (4x2), warp tile 32x64.
#define DEC_STAGES 4
#define DEC_STG_BYTES 20480
#define DEC_SMEM (512 + DEC_STAGES*DEC_STG_BYTES)
#define DEC_NCHUNK (KA/32)        // 32

__device__ __forceinline__ uint32_t s2u(const void* p) {
    uint32_t a;
    asm("{ .reg .u64 t; cvta.to.shared.u64 t, %1; cvt.u32.u64 %0, t; }" : "=r"(a) : "l"(p));
    return a;
}
__device__ __forceinline__ void cp16(uint32_t dst, const void* src) {
    asm volatile("cp.async.cg.shared.global [%0], [%1], 16;" :: "r"(dst), "l"(src));
}
__device__ __forceinline__ void cp_commit() {
    asm volatile("cp.async.commit_group;" ::: "memory");
}
template <int N> __device__ __forceinline__ void cp_wait() {
    asm volatile("cp.async.wait_group %0;" :: "n"(N) : "memory");
}
__device__ __forceinline__ void ldmx4(uint32_t* r, uint32_t a) {
    asm volatile("ldmatrix.sync.aligned.m8n8.x4.shared.b16 {%0,%1,%2,%3}, [%4];"
        : "=r"(r[0]), "=r"(r[1]), "=r"(r[2]), "=r"(r[3]) : "r"(a));
}
__device__ __forceinline__ void mma16816(float* c, const uint32_t* a, uint32_t b0, uint32_t b1) {
    asm volatile("mma.sync.aligned.m16n8k16.row.col.f32.f16.f16.f32 "
        "{%0,%1,%2,%3}, {%4,%5,%6,%7}, {%8,%9}, {%0,%1,%2,%3};"
        : "+f"(c[0]), "+f"(c[1]), "+f"(c[2]), "+f"(c[3])
        : "r"(a[0]), "r"(a[1]), "r"(a[2]), "r"(a[3]), "r"(b0), "r"(b1));
}

__device__ __forceinline__ void dec_load(uint32_t base, const char* Ag, const char* Bg,
                                         int kc, int r_, int seg) {
    const size_t koff = (size_t)kc * 64;
    cp16(base + r_*80 + seg*16,        Ag + (size_t)r_      * (KA*2) + koff + seg*16);
    cp16(base + (r_+64)*80 + seg*16,   Ag + (size_t)(r_+64) * (KA*2) + koff + seg*16);
    cp16(base + 10240 + r_*80 + seg*16,      Bg + (size_t)r_      * (KB*2) + koff + seg*16);
    cp16(base + 10240 + (r_+64)*80 + seg*16, Bg + (size_t)(r_+64) * (KB*2) + koff + seg*16);
}

__global__ void __launch_bounds__(256, 2) decoder_hmma(const float* __restrict__ bias,
                                                       float* __restrict__ out) {
    extern __shared__ __align__(16) char smem[];
    float* sbias = (float*)smem;
    const uint32_t D0 = s2u(smem) + 512;
    const int tid = threadIdx.x;
    const int wid = tid >> 5, lid = tid & 31;
    const int m0 = blockIdx.x * 128, n0 = blockIdx.y * 128;
    const int wm = wid >> 1, wn = wid & 1;

    if (tid < 128) sbias[tid] = bias[n0 + tid];

    const char* Ag = (const char*)(g_Acat + (size_t)m0 * KA);
    const char* Bg = (const char*)(g_Bcat + (size_t)n0 * KB);
    const int r_ = tid >> 2, seg = tid & 3;

    float acc[2][8][4];
#pragma unroll
    for (int i = 0; i < 2; i++)
#pragma unroll
        for (int j = 0; j < 8; j++)
#pragma unroll
            for (int q = 0; q < 4; q++) acc[i][j][q] = 0.f;

    // prologue: stages 0..2
#pragma unroll
    for (int s = 0; s < DEC_STAGES - 1; s++) {
        dec_load(D0 + s*DEC_STG_BYTES, Ag, Bg, s, r_, seg);
        cp_commit();
    }

    const int quad = lid >> 3, r8 = lid & 7;
    const uint32_t a_row = wm*32 + (quad & 1)*8 + r8;
    const uint32_t a_kb  = (quad >> 1) * 16;
    const uint32_t b_row = wn*64 + (quad >> 1)*8 + r8;
    const uint32_t b_kb  = (quad & 1) * 16;

    for (int kc = 0; kc < DEC_NCHUNK; kc++) {
        const int s = kc & (DEC_STAGES - 1);
        cp_wait<DEC_STAGES - 2>();
        __syncthreads();
        if (kc + DEC_STAGES - 1 < DEC_NCHUNK) {
            dec_load(D0 + ((kc + DEC_STAGES - 1) & (DEC_STAGES - 1))*DEC_STG_BYTES,
                     Ag, Bg, kc + DEC_STAGES - 1, r_, seg);
        }
        cp_commit();

        const uint32_t sA = D0 + s * DEC_STG_BYTES;
        const uint32_t sB = sA + 10240;
#pragma unroll
        for (int kk = 0; kk < 2; kk++) {
            uint32_t A0[4], A1[4], Bf[4][4];
            uint32_t aaddr = sA + a_row*80 + kk*32 + a_kb;
            ldmx4(A0, aaddr);
            ldmx4(A1, aaddr + 16*80);
            uint32_t baddr = sB + b_row*80 + kk*32 + b_kb;
#pragma unroll
            for (int p = 0; p < 4; p++) ldmx4(Bf[p], baddr + p*16*80);
#pragma unroll
            for (int ni = 0; ni < 8; ni++) {
                uint32_t b0 = Bf[ni >> 1][(ni & 1)*2 + 0];
                uint32_t b1 = Bf[ni >> 1][(ni & 1)*2 + 1];
                mma16816(acc[0][ni], A0, b0, b1);
                mma16816(acc[1][ni], A1, b0, b1);
            }
        }
    }
    cp_wait<0>();

    // epilogue: bias + row remap (m = t*16+b -> out row b*256+t)
    const int mrow0 = m0 + wm*32 + (lid >> 2);
    const int ncol0 = wn*64 + 2*(lid & 3);
#pragma unroll
    for (int mi = 0; mi < 2; mi++) {
        int mA = mrow0 + mi*16, mB = mA + 8;
        float* oA = out + (size_t)((mA & 15)*SEQLEN + (mA >> 4)) * VOCAB + n0;
        float* oB = out + (size_t)((mB & 15)*SEQLEN + (mB >> 4)) * VOCAB + n0;
#pragma unroll
        for (int ni = 0; ni < 8; ni++) {
            int nn = ncol0 + ni*8;
            float2 vA = make_float2(acc[mi][ni][0] + sbias[nn], acc[mi][ni][1] + sbias[nn+1]);
            float2 vB = make_float2(acc[mi][ni][2] + sbias[nn], acc[mi][ni][3] + sbias[nn+1]);
            *(float2*)(oA + nn) = vA;
            *(float2*)(oB + nn) = vB;
        }
    }
}

// ======================= launch ============================================
extern "C" void kernel_launch(void* const* d_in, const int* in_sizes, int n_in,
                              void* d_out, int out_size) {
    const int*   inp = (const int*)d_in[0];
    const float* emb = (const float*)d_in[1];
    const float* A   = (const float*)d_in[2];
    const float* B   = (const float*)d_in[3];
    const float* C   = (const float*)d_in[4];
    const float* U   = (const float*)d_in[5];
    const float* V   = (const float*)d_in[6];
    const float* dv  = (const float*)d_in[7];
    const float* Wd  = (const float*)d_in[8];
    const float* bd  = (const float*)d_in[9];
    float* out = (float*)d_out;

    cudaFuncSetAttribute(rnn_kernel, cudaFuncAttributeMaxDynamicSharedMemorySize,
                         RNN_SMEM_BYTES);
    cudaFuncSetAttribute(decoder_hmma, cudaFuncAttributeMaxDynamicSharedMemorySize,
                         DEC_SMEM);

    conv_W<<<dim3(VOCAB/32, HID/32), 256>>>(Wd);

    dim3 gXU(NTOK/64, HID/64);
    gather_gemm<HID, true><<<gXU, 256>>>(inp, emb, U, dv);
    dim3 gXB(NTOK/64, RANK/64);
    gather_gemm<RANK, false><<<gXB, 256>>>(inp, emb, B, nullptr);

    rnn_kernel<<<RNN_BLOCKS, 256, RNN_SMEM_BYTES>>>(A, C, V);

    dim3 gDec(NTOK/128, VOCAB/128);
    decoder_hmma<<<gDec, 256, DEC_SMEM>>>(bd, out);
}

// round 11
// speedup vs baseline: 1.7238x; 1.0667x over previous
#include <cuda_runtime.h>
#include <cuda_fp16.h>
#include <cstdint>
#include <cstddef>

#define VOCAB 32000
#define HID   1024
#define EMB   512
#define RANK  64
#define BATCH 16
#define SEQLEN 256
#define NTOK  (BATCH*SEQLEN)
#define KA    1024
#define KB    1024

#define RNN_BLOCKS 128
// smem floats: Vp 8192, Asm 9216, Cs 520, gs 1040, red 8448
#define OFF_VP 0
#define OFF_A  8192
#define OFF_C  17408
#define OFF_G  17928
#define OFF_R  18968
#define RNN_SMEM_FLOATS 27416
#define RNN_SMEM_BYTES  (RNN_SMEM_FLOATS*4)

__device__ __align__(16) float g_XU[NTOK*HID];
__device__ __align__(16) float g_XB[NTOK*RANK];
__device__ __align__(16) float g_h[2][BATCH*HID];          // row-major (phase-1)
__device__ __align__(16) float g_hP[2][4][HID*4];          // plane: [bg2][j*4 + b&3]
__device__ __align__(16) float g_gbuf[BATCH*RANK];
__device__ __align__(16) __half g_Acat[(size_t)NTOK*KA];
__device__ __align__(16) __half g_Bcat[(size_t)VOCAB*KB];
__device__ unsigned g_bar_arrive = 0;
__device__ unsigned g_bar_gen    = 0;

__device__ __forceinline__ void grid_bar() {
    __threadfence();
    __syncthreads();
    if (threadIdx.x == 0) {
        volatile unsigned* genp = (volatile unsigned*)&g_bar_gen;
        unsigned gen = *genp;
        unsigned arrived = atomicAdd(&g_bar_arrive, 1u);
        if (arrived == RNN_BLOCKS - 1) {
            atomicExch(&g_bar_arrive, 0u);
            __threadfence();
            atomicAdd(&g_bar_gen, 1u);
        } else {
            while (*genp == gen) { }
            __threadfence();
        }
    }
    __syncthreads();
}

__device__ __forceinline__ unsigned long long pk2(float lo, float hi) {
    unsigned long long r;
    asm("mov.b64 %0, {%1, %2};" : "=l"(r) : "f"(lo), "f"(hi));
    return r;
}
__device__ __forceinline__ void fma2(unsigned long long& d, unsigned long long a, unsigned long long b) {
    asm("fma.rn.f32x2 %0, %1, %2, %0;" : "+l"(d) : "l"(a), "l"(b));
}
__device__ __forceinline__ float2 upk2(unsigned long long v) {
    float2 r;
    asm("mov.b64 {%0, %1}, %2;" : "=f"(r.x), "=f"(r.y) : "l"(v));
    return r;
}

// ======================= precompute: XU, XB ================================
template <int N_, bool HAS_BIAS>
__global__ __launch_bounds__(256) void gather_gemm(const int* __restrict__ inp,
                                                   const float* __restrict__ emb,
                                                   const float* __restrict__ W,
                                                   const float* __restrict__ bias) {
    __shared__ float As[16][65];
    __shared__ float Bs[16][68];
    __shared__ int   toks[64];
    float* outp = (N_ == RANK) ? g_XB : g_XU;

    const int tid = threadIdx.x;
    const int m0 = blockIdx.x * 64, n0 = blockIdx.y * 64;
    if (tid < 64) {
        int m = m0 + tid;
        toks[tid] = inp[(m & 15) * SEQLEN + (m >> 4)];
    }
    __syncthreads();

    const int ty = tid >> 4, tx = tid & 15;
    const int am = tid >> 2, akq = tid & 3;
    const int bk = tid >> 4, bn = tid & 15;
    float acc[4][4] = {};

    for (int k0 = 0; k0 < EMB; k0 += 16) {
        float4 av = *(const float4*)&emb[(size_t)toks[am] * EMB + k0 + akq * 4];
        float4 bv = *(const float4*)&W[(size_t)(k0 + bk) * N_ + n0 + bn * 4];
        __syncthreads();
        As[akq*4+0][am] = av.x; As[akq*4+1][am] = av.y;
        As[akq*4+2][am] = av.z; As[akq*4+3][am] = av.w;
        *(float4*)&Bs[bk][bn*4] = bv;
        __syncthreads();
#pragma unroll
        for (int kk = 0; kk < 16; kk++) {
            float a0 = As[kk][ty*4+0], a1 = As[kk][ty*4+1];
            float a2 = As[kk][ty*4+2], a3 = As[kk][ty*4+3];
            float4 b4 = *(const float4*)&Bs[kk][tx*4];
            acc[0][0] += a0*b4.x; acc[0][1] += a0*b4.y; acc[0][2] += a0*b4.z; acc[0][3] += a0*b4.w;
            acc[1][0] += a1*b4.x; acc[1][1] += a1*b4.y; acc[1][2] += a1*b4.z; acc[1][3] += a1*b4.w;
            acc[2][0] += a2*b4.x; acc[2][1] += a2*b4.y; acc[2][2] += a2*b4.z; acc[2][3] += a2*b4.w;
            acc[3][0] += a3*b4.x; acc[3][1] += a3*b4.y; acc[3][2] += a3*b4.z; acc[3][3] += a3*b4.w;
        }
    }

    float4 bb = make_float4(0.f,0.f,0.f,0.f);
    if (HAS_BIAS) bb = *(const float4*)&bias[n0 + tx*4];
#pragma unroll
    for (int i = 0; i < 4; i++) {
        int m = m0 + ty*4 + i;
        float4 o = make_float4(acc[i][0]+bb.x, acc[i][1]+bb.y, acc[i][2]+bb.z, acc[i][3]+bb.w);
        *(float4*)&outp[(size_t)m * N_ + n0 + tx*4] = o;
    }
}

// ======================= recurrence ========================================
__global__ __launch_bounds__(256) void rnn_kernel(const float* __restrict__ A,
                                                  const float* __restrict__ C,
                                                  const float* __restrict__ V) {
    extern __shared__ float sm[];
    float* Vp  = sm + OFF_VP;  // permuted: [(((cc*2+ks)*4+i)*32+kg2)*4 + q]
    float* Asm = sm + OFF_A;   // [1024][9]
    float* Cs  = sm + OFF_C;   // [8][65]
    float* gs  = sm + OFF_G;   // [16][65]
    float* red = sm + OFF_R;   // [256][33]

    const int c = blockIdx.x, tid = threadIdx.x;
    const int col0  = c * 8;
    const int rbase = (c & 7) * 8;
    const int bmine = c >> 3;

    // V permuted into smem; A slice
    for (int idx = tid; idx < 8192; idx += 256) {
        int cc = idx & 7, j = idx >> 3;
        int ksj = j >> 9, ij = (j >> 7) & 3, qj = (j >> 5) & 3, kj = j & 31;
        Vp[(((cc*2 + ksj)*4 + ij)*32 + kj)*4 + qj] = V[(size_t)j*HID + col0 + cc];
        Asm[j*9 + cc] = A[j*RANK + rbase + cc];
    }
    for (int idx = tid; idx < 512; idx += 256) {
        int ci = idx >> 6, r = idx & 63;
        Cs[ci*65 + r] = C[(col0 + ci)*RANK + r];
    }
    if (tid < 128) {
        g_h[0][c*128 + tid] = 0.0f;
        ((float*)g_hP[0])[c*128 + tid] = 0.0f;
    }
    __syncthreads();
    grid_bar();

    const int lane = tid & 31, w = tid >> 5;
    const int bg2 = tid >> 6, ks = (tid >> 5) & 1, kg2 = tid & 31;
    const int b128 = tid >> 3, ci128 = tid & 7;     // combine mapping

    for (int t = 0; t < SEQLEN; t++) {
        const int p = t & 1;
        // prefetch XU / XB early (hide DRAM latency)
        float xu = 0.f, xb = 0.f;
        if (tid < 128)
            xu = __ldcg(&g_XU[((size_t)t*BATCH + b128)*HID + col0 + ci128]);
        if (lane == 0)
            xb = __ldcg(&g_XB[((size_t)t*BATCH + bmine)*RANK + rbase + w]);

        // phase 1: g[bmine, rbase+w] = (h@A) * XB
        {
            const float* hrow = g_h[p] + bmine * HID;
            float s = 0.f;
#pragma unroll 8
            for (int j = lane; j < HID; j += 32)
                s += __ldcg(hrow + j) * Asm[j*9 + w];
#pragma unroll
            for (int off = 16; off; off >>= 1)
                s += __shfl_xor_sync(0xffffffffu, s, off);
            if (lane == 0)
                __stcg(&g_gbuf[bmine*RANK + rbase + w], s * xb);
        }
        grid_bar();

        // phase 2: h_new = tanh(XU + g@C^T + h@V) for this CTA's 8 cols
        {
            // stage gs (sync deferred to the reduction sync)
            for (int idx = tid; idx < 1024; idx += 256)
                gs[(idx >> 6)*65 + (idx & 63)] = __ldcg(&g_gbuf[idx]);

            const float4* hp = (const float4*)g_hP[p][bg2];
            unsigned long long acc2[8][2];
#pragma unroll
            for (int cc = 0; cc < 8; cc++) { acc2[cc][0] = 0ull; acc2[cc][1] = 0ull; }

#pragma unroll
            for (int i = 0; i < 4; i++) {
                const int jb = ks*512 + i*128 + kg2;
                float4 hv[4], vv[8];
#pragma unroll
                for (int q = 0; q < 4; q++)
                    hv[q] = __ldcg(&hp[jb + q*32]);
#pragma unroll
                for (int cc = 0; cc < 8; cc++)
                    vv[cc] = *(const float4*)&Vp[(((cc*2 + ks)*4 + i)*32 + kg2)*4];

                unsigned long long h01[4], h23[4];
#pragma unroll
                for (int q = 0; q < 4; q++) {
                    h01[q] = pk2(hv[q].x, hv[q].y);
                    h23[q] = pk2(hv[q].z, hv[q].w);
                }
#pragma unroll
                for (int cc = 0; cc < 8; cc++) {
                    const float* vq = (const float*)&vv[cc];
#pragma unroll
                    for (int q = 0; q < 4; q++) {
                        unsigned long long vd = pk2(vq[q], vq[q]);
                        fma2(acc2[cc][0], vd, h01[q]);
                        fma2(acc2[cc][1], vd, h23[q]);
                    }
                }
            }
#pragma unroll
            for (int cc = 0; cc < 8; cc++) {
                float2 a0 = upk2(acc2[cc][0]), a1 = upk2(acc2[cc][1]);
                red[tid*33 + cc*4 + 0] = a0.x;
                red[tid*33 + cc*4 + 1] = a0.y;
                red[tid*33 + cc*4 + 2] = a1.x;
                red[tid*33 + cc*4 + 3] = a1.y;
            }
            __syncthreads();

            if (tid < 128) {
                const int b = b128, ci = ci128;
                const int bgo = b >> 2, slot = ci*4 + (b & 3);
                const int ii = col0 + ci;
                float s = 0.f;
#pragma unroll 16
                for (int u = 0; u < 64; u++) {
                    int src = (bgo*2 + (u >> 5))*32 + (u & 31);
                    s += red[src*33 + slot];
                }
#pragma unroll 16
                for (int r = 0; r < RANK; r++)
                    s += gs[b*65 + r] * Cs[ci*65 + r];
                s += xu;
                float hn = tanhf(s);
                __stcg(&g_h[p^1][b*HID + ii], hn);
                __stcg(&g_hP[p^1][b >> 2][ii*4 + (b & 3)], hn);
                g_Acat[((size_t)t*BATCH + b)*KA + ii] = __float2half(hn);
            }
        }
        grid_bar();
    }
}

// ======================= W operand preparation =============================
__global__ __launch_bounds__(256) void conv_W(const float* __restrict__ W) {
    __shared__ float tile[32][33];
    const int bx = blockIdx.x, by = blockIdx.y;
    const int tx = threadIdx.x & 31, ty = threadIdx.x >> 5;
    int n = bx*32 + tx;
#pragma unroll
    for (int r = 0; r < 32; r += 8) {
        int k = by*32 + ty + r;
        tile[ty + r][tx] = W[(size_t)k*VOCAB + n];
    }
    __syncthreads();
#pragma unroll
    for (int r = 0; r < 32; r += 8) {
        int n2 = bx*32 + ty + r;
        int k2 = by*32 + tx;
        g_Bcat[(size_t)n2*KB + k2] = __float2half(tile[tx][ty + r]);
    }
}

// ======================= HMMA decoder GEMM =================================
#define DEC_STAGES 4
#define DEC_STG_BYTES 20480
#define DEC_SMEM (512 + DEC_STAGES*DEC_STG_BYTES)
#define DEC_NCHUNK (KA/32)

__device__ __forceinline__ uint32_t s2u(const void* p) {
    uint32_t a;
    asm("{ .reg .u64 t; cvta.to.shared.u64 t, %1; cvt.u32.u64 %0, t; }" : "=r"(a) : "l"(p));
    return a;
}
__device__ __forceinline__ void cp16(uint32_t dst, const void* src) {
    asm volatile("cp.async.cg.shared.global [%0], [%1], 16;" :: "r"(dst), "l"(src));
}
__device__ __forceinline__ void cp_commit() {
    asm volatile("cp.async.commit_group;" ::: "memory");
}
template <int N> __device__ __forceinline__ void cp_wait() {
    asm volatile("cp.async.wait_group %0;" :: "n"(N) : "memory");
}
__device__ __forceinline__ void ldmx4(uint32_t* r, uint32_t a) {
    asm volatile("ldmatrix.sync.aligned.m8n8.x4.shared.b16 {%0,%1,%2,%3}, [%4];"
        : "=r"(r[0]), "=r"(r[1]), "=r"(r[2]), "=r"(r[3]) : "r"(a));
}
__device__ __forceinline__ void mma16816(float* c, const uint32_t* a, uint32_t b0, uint32_t b1) {
    asm volatile("mma.sync.aligned.m16n8k16.row.col.f32.f16.f16.f32 "
        "{%0,%1,%2,%3}, {%4,%5,%6,%7}, {%8,%9}, {%0,%1,%2,%3};"
        : "+f"(c[0]), "+f"(c[1]), "+f"(c[2]), "+f"(c[3])
        : "r"(a[0]), "r"(a[1]), "r"(a[2]), "r"(a[3]), "r"(b0), "r"(b1));
}

__device__ __forceinline__ void dec_load(uint32_t base, const char* Ag, const char* Bg,
                                         int kc, int r_, int seg) {
    const size_t koff = (size_t)kc * 64;
    cp16(base + r_*80 + seg*16,        Ag + (size_t)r_      * (KA*2) + koff + seg*16);
    cp16(base + (r_+64)*80 + seg*16,   Ag + (size_t)(r_+64) * (KA*2) + koff + seg*16);
    cp16(base + 10240 + r_*80 + seg*16,      Bg + (size_t)r_      * (KB*2) + koff + seg*16);
    cp16(base + 10240 + (r_+64)*80 + seg*16, Bg + (size_t)(r_+64) * (KB*2) + koff + seg*16);
}

__global__ void __launch_bounds__(256, 2) decoder_hmma(const float* __restrict__ bias,
                                                       float* __restrict__ out) {
    extern __shared__ __align__(16) char smem[];
    float* sbias = (float*)smem;
    const uint32_t D0 = s2u(smem) + 512;
    const int tid = threadIdx.x;
    const int wid = tid >> 5, lid = tid & 31;
    const int m0 = blockIdx.x * 128, n0 = blockIdx.y * 128;
    const int wm = wid >> 1, wn = wid & 1;

    if (tid < 128) sbias[tid] = bias[n0 + tid];

    const char* Ag = (const char*)(g_Acat + (size_t)m0 * KA);
    const char* Bg = (const char*)(g_Bcat + (size_t)n0 * KB);
    const int r_ = tid >> 2, seg = tid & 3;

    float acc[2][8][4];
#pragma unroll
    for (int i = 0; i < 2; i++)
#pragma unroll
        for (int j = 0; j < 8; j++)
#pragma unroll
            for (int q = 0; q < 4; q++) acc[i][j][q] = 0.f;

#pragma unroll
    for (int s = 0; s < DEC_STAGES - 1; s++) {
        dec_load(D0 + s*DEC_STG_BYTES, Ag, Bg, s, r_, seg);
        cp_commit();
    }

    const int quad = lid >> 3, r8 = lid & 7;
    const uint32_t a_row = wm*32 + (quad & 1)*8 + r8;
    const uint32_t a_kb  = (quad >> 1) * 16;
    const uint32_t b_row = wn*64 + (quad >> 1)*8 + r8;
    const uint32_t b_kb  = (quad & 1) * 16;

    for (int kc = 0; kc < DEC_NCHUNK; kc++) {
        const int s = kc & (DEC_STAGES - 1);
        cp_wait<DEC_STAGES - 2>();
        __syncthreads();
        if (kc + DEC_STAGES - 1 < DEC_NCHUNK) {
            dec_load(D0 + ((kc + DEC_STAGES - 1) & (DEC_STAGES - 1))*DEC_STG_BYTES,
                     Ag, Bg, kc + DEC_STAGES - 1, r_, seg);
        }
        cp_commit();

        const uint32_t sA = D0 + s * DEC_STG_BYTES;
        const uint32_t sB = sA + 10240;
#pragma unroll
        for (int kk = 0; kk < 2; kk++) {
            uint32_t A0[4], A1[4], Bf[4][4];
            uint32_t aaddr = sA + a_row*80 + kk*32 + a_kb;
            ldmx4(A0, aaddr);
            ldmx4(A1, aaddr + 16*80);
            uint32_t baddr = sB + b_row*80 + kk*32 + b_kb;
#pragma unroll
            for (int p = 0; p < 4; p++) ldmx4(Bf[p], baddr + p*16*80);
#pragma unroll
            for (int ni = 0; ni < 8; ni++) {
                uint32_t b0 = Bf[ni >> 1][(ni & 1)*2 + 0];
                uint32_t b1 = Bf[ni >> 1][(ni & 1)*2 + 1];
                mma16816(acc[0][ni], A0, b0, b1);
                mma16816(acc[1][ni], A1, b0, b1);
            }
        }
    }
    cp_wait<0>();

    const int mrow0 = m0 + wm*32 + (lid >> 2);
    const int ncol0 = wn*64 + 2*(lid & 3);
#pragma unroll
    for (int mi = 0; mi < 2; mi++) {
        int mA = mrow0 + mi*16, mB = mA + 8;
        float* oA = out + (size_t)((mA & 15)*SEQLEN + (mA >> 4)) * VOCAB + n0;
        float* oB = out + (size_t)((mB & 15)*SEQLEN + (mB >> 4)) * VOCAB + n0;
#pragma unroll
        for (int ni = 0; ni < 8; ni++) {
            int nn = ncol0 + ni*8;
            float2 vA = make_float2(acc[mi][ni][0] + sbias[nn], acc[mi][ni][1] + sbias[nn+1]);
            float2 vB = make_float2(acc[mi][ni][2] + sbias[nn], acc[mi][ni][3] + sbias[nn+1]);
            *(float2*)(oA + nn) = vA;
            *(float2*)(oB + nn) = vB;
        }
    }
}

// ======================= launch ============================================
extern "C" void kernel_launch(void* const* d_in, const int* in_sizes, int n_in,
                              void* d_out, int out_size) {
    const int*   inp = (const int*)d_in[0];
    const float* emb = (const float*)d_in[1];
    const float* A   = (const float*)d_in[2];
    const float* B   = (const float*)d_in[3];
    const float* C   = (const float*)d_in[4];
    const float* U   = (const float*)d_in[5];
    const float* V   = (const float*)d_in[6];
    const float* dv  = (const float*)d_in[7];
    const float* Wd  = (const float*)d_in[8];
    const float* bd  = (const float*)d_in[9];
    float* out = (float*)d_out;

    cudaFuncSetAttribute(rnn_kernel, cudaFuncAttributeMaxDynamicSharedMemorySize,
                         RNN_SMEM_BYTES);
    cudaFuncSetAttribute(decoder_hmma, cudaFuncAttributeMaxDynamicSharedMemorySize,
                         DEC_SMEM);

    conv_W<<<dim3(VOCAB/32, HID/32), 256>>>(Wd);

    dim3 gXU(NTOK/64, HID/64);
    gather_gemm<HID, true><<<gXU, 256>>>(inp, emb, U, dv);
    dim3 gXB(NTOK/64, RANK/64);
    gather_gemm<RANK, false><<<gXB, 256>>>(inp, emb, B, nullptr);

    rnn_kernel<<<RNN_BLOCKS, 256, RNN_SMEM_BYTES>>>(A, C, V);

    dim3 gDec(NTOK/128, VOCAB/128);
    decoder_hmma<<<gDec, 256, DEC_SMEM>>>(bd, out);
}